// round 10
// baseline (speedup 1.0000x reference)
#include <cuda_runtime.h>
#include <cuda_bf16.h>
#include <stdint.h>

#ifndef CLAMP_VAL
#define CLAMP_VAL 10000.0f
#endif

__device__ __forceinline__ float clampv(float v) {
    return fminf(fmaxf(v, -CLAMP_VAL), CLAMP_VAL);
}

// ---------------------------------------------------------------------------
// Fast path: in_w = 8192, out_w = 8191. One block per row, TPB=128.
// Aligned 128-bit on BOTH sides; per-row 4-byte phase (lead = row & 3)
// resolved by register shuffle from two overlapping aligned input vectors.
// Loads default-cached (overlap line = L1 hit); stores evict-first.
// Structure identical to the measured optimum (R4/R7/R9: 39.8-40.0us kernel,
// 32 regs, 6.7 TB/s effective = 84% of HBM spec); TPB 256->128 tests
// occupancy/wave quantization as the final untested micro-lever.
// ---------------------------------------------------------------------------
constexpr int TPB = 128;

__global__ void __launch_bounds__(TPB)
binagg_row_kernel(const float4* __restrict__ x4, float* __restrict__ out)
{
    const unsigned r = blockIdx.x;
    const float4* xrow = x4 + (size_t)r * 2048u;           // 8192 floats / 4
    const float*  xs   = (const float*)xrow;
    float*        orow = out + (size_t)r * 8191u;
    const int tid  = threadIdx.x;
    const int lead = (int)(r & 3u);                         // out-row phase

    // Head: cols 0..lead-1 (0..3 scalars)
    if (tid < lead) orow[tid] = clampv(__ldg(xs + tid));

    // Aligned out-vectors covering cols [lead, lead+4*count), max col <= 8189
    const int count = ((8186 - lead) >> 2) + 1;             // 2047 or 2046
    float4* ov = (float4*)(orow + lead);                    // 16B aligned

    if (lead == 0) {
        #pragma unroll 4
        for (int v = tid; v < count; v += TPB) {
            float4 a = __ldg(&xrow[v]);
            float4 s = { clampv(a.x), clampv(a.y), clampv(a.z), clampv(a.w) };
            __stcs(&ov[v], s);
        }
    } else if (lead == 1) {
        #pragma unroll 4
        for (int v = tid; v < count; v += TPB) {
            float4 a = __ldg(&xrow[v]);
            float4 b = __ldg(&xrow[v + 1]);
            float4 s = { clampv(a.y), clampv(a.z), clampv(a.w), clampv(b.x) };
            __stcs(&ov[v], s);
        }
    } else if (lead == 2) {
        #pragma unroll 4
        for (int v = tid; v < count; v += TPB) {
            float4 a = __ldg(&xrow[v]);
            float4 b = __ldg(&xrow[v + 1]);
            float4 s = { clampv(a.z), clampv(a.w), clampv(b.x), clampv(b.y) };
            __stcs(&ov[v], s);
        }
    } else {
        #pragma unroll 4
        for (int v = tid; v < count; v += TPB) {
            float4 a = __ldg(&xrow[v]);
            float4 b = __ldg(&xrow[v + 1]);
            float4 s = { clampv(a.w), clampv(b.x), clampv(b.y), clampv(b.z) };
            __stcs(&ov[v], s);
        }
    }

    // Tail: cols [lead + 4*count, 8190]; col 8190 = mean of last two inputs
    const int tstart = lead + 4 * count;
    for (int c = tstart + tid; c <= 8190; c += TPB) {
        float val = (c == 8190)
                  ? 0.5f * (__ldg(xs + 8190) + __ldg(xs + 8191))
                  : __ldg(xs + c);
        orow[c] = clampv(val);
    }
}

// ---------------------------------------------------------------------------
// Generic fallback (any in_w/out_w): flat output indexing, scalar.
// ---------------------------------------------------------------------------
__global__ void __launch_bounds__(256)
binagg_generic_kernel(const float* __restrict__ x, float* __restrict__ out,
                      int in_w, int out_w, unsigned total)
{
    unsigned oo = blockIdx.x * blockDim.x + threadIdx.x;
    if (oo >= total) return;
    unsigned r = oo / (unsigned)out_w;
    unsigned c = oo - r * (unsigned)out_w;
    const float* xr = x + (size_t)r * (size_t)in_w;
    float val;
    if (c < (unsigned)(out_w - 1)) {
        val = __ldg(xr + c);
    } else {
        float s = 0.0f;
        for (int k = out_w - 1; k < in_w; ++k) s += __ldg(xr + k);
        val = s / (float)(in_w - out_w + 1);
    }
    out[oo] = clampv(val);
}

extern "C" void kernel_launch(void* const* d_in, const int* in_sizes, int n_in,
                              void* d_out, int out_size)
{
    const float* x = (const float*)d_in[0];
    float* out = (float*)d_out;

    const int in_w = 8192;
    int batch = in_sizes[0] / in_w;
    int out_w = (batch > 0) ? out_size / batch : 0;

    bool fast = (batch > 0) &&
                (batch * in_w == in_sizes[0]) &&
                (out_w == in_w - 1) &&
                ((size_t)batch * (size_t)out_w == (size_t)out_size);

    if (fast) {
        binagg_row_kernel<<<batch, TPB>>>((const float4*)x, out);
    } else {
        int iw = in_sizes[0];
        int ow = out_size;
        for (int cand = 8192; cand >= 1; cand >>= 1) {
            if (in_sizes[0] % cand == 0) {
                int bb = in_sizes[0] / cand;
                if (bb > 0 && out_size % bb == 0) { iw = cand; ow = out_size / bb; break; }
            }
        }
        unsigned total = (unsigned)out_size;
        unsigned blocks = (total + 255) / 256;
        binagg_generic_kernel<<<blocks, 256>>>(x, out, iw, ow, total);
    }
}

// round 11
// speedup vs baseline: 1.0555x; 1.0555x over previous
#include <cuda_runtime.h>
#include <cuda_bf16.h>
#include <stdint.h>

#ifndef CLAMP_VAL
#define CLAMP_VAL 10000.0f
#endif

__device__ __forceinline__ float clampv(float v) {
    return fminf(fmaxf(v, -CLAMP_VAL), CLAMP_VAL);
}

// ---------------------------------------------------------------------------
// Fast path: in_w = 8192, out_w = 8191. One block per row, TPB=256.
// Aligned 128-bit on BOTH sides; per-row 4-byte phase (lead = row & 3)
// resolved by register shuffle from two overlapping aligned input vectors.
// Loads default-cached (overlap line = L1 hit); stores evict-first.
// MEASURED OPTIMUM across 10 rounds (39.78-40.0us kernel, 32 regs, occ 75%,
// 6.74 TB/s effective = 84% of HBM spec = mixed read/write DRAM ceiling).
// Known regressions: TPB 128/512, unroll 8, __ldcs loads, front-batching,
// rows-per-block>1, narrow overlap loads. Do not modify.
// ---------------------------------------------------------------------------
constexpr int TPB = 256;

__global__ void __launch_bounds__(TPB)
binagg_row_kernel(const float4* __restrict__ x4, float* __restrict__ out)
{
    const unsigned r = blockIdx.x;
    const float4* xrow = x4 + (size_t)r * 2048u;           // 8192 floats / 4
    const float*  xs   = (const float*)xrow;
    float*        orow = out + (size_t)r * 8191u;
    const int tid  = threadIdx.x;
    const int lead = (int)(r & 3u);                         // out-row phase

    // Head: cols 0..lead-1 (0..3 scalars)
    if (tid < lead) orow[tid] = clampv(__ldg(xs + tid));

    // Aligned out-vectors covering cols [lead, lead+4*count), max col <= 8189
    const int count = ((8186 - lead) >> 2) + 1;             // 2047 or 2046
    float4* ov = (float4*)(orow + lead);                    // 16B aligned

    if (lead == 0) {
        #pragma unroll 4
        for (int v = tid; v < count; v += TPB) {
            float4 a = __ldg(&xrow[v]);
            float4 s = { clampv(a.x), clampv(a.y), clampv(a.z), clampv(a.w) };
            __stcs(&ov[v], s);
        }
    } else if (lead == 1) {
        #pragma unroll 4
        for (int v = tid; v < count; v += TPB) {
            float4 a = __ldg(&xrow[v]);
            float4 b = __ldg(&xrow[v + 1]);
            float4 s = { clampv(a.y), clampv(a.z), clampv(a.w), clampv(b.x) };
            __stcs(&ov[v], s);
        }
    } else if (lead == 2) {
        #pragma unroll 4
        for (int v = tid; v < count; v += TPB) {
            float4 a = __ldg(&xrow[v]);
            float4 b = __ldg(&xrow[v + 1]);
            float4 s = { clampv(a.z), clampv(a.w), clampv(b.x), clampv(b.y) };
            __stcs(&ov[v], s);
        }
    } else {
        #pragma unroll 4
        for (int v = tid; v < count; v += TPB) {
            float4 a = __ldg(&xrow[v]);
            float4 b = __ldg(&xrow[v + 1]);
            float4 s = { clampv(a.w), clampv(b.x), clampv(b.y), clampv(b.z) };
            __stcs(&ov[v], s);
        }
    }

    // Tail: cols [lead + 4*count, 8190]; col 8190 = mean of last two inputs
    const int tstart = lead + 4 * count;
    for (int c = tstart + tid; c <= 8190; c += TPB) {
        float val = (c == 8190)
                  ? 0.5f * (__ldg(xs + 8190) + __ldg(xs + 8191))
                  : __ldg(xs + c);
        orow[c] = clampv(val);
    }
}

// ---------------------------------------------------------------------------
// Generic fallback (any in_w/out_w): flat output indexing, scalar.
// ---------------------------------------------------------------------------
__global__ void __launch_bounds__(256)
binagg_generic_kernel(const float* __restrict__ x, float* __restrict__ out,
                      int in_w, int out_w, unsigned total)
{
    unsigned oo = blockIdx.x * blockDim.x + threadIdx.x;
    if (oo >= total) return;
    unsigned r = oo / (unsigned)out_w;
    unsigned c = oo - r * (unsigned)out_w;
    const float* xr = x + (size_t)r * (size_t)in_w;
    float val;
    if (c < (unsigned)(out_w - 1)) {
        val = __ldg(xr + c);
    } else {
        float s = 0.0f;
        for (int k = out_w - 1; k < in_w; ++k) s += __ldg(xr + k);
        val = s / (float)(in_w - out_w + 1);
    }
    out[oo] = clampv(val);
}

extern "C" void kernel_launch(void* const* d_in, const int* in_sizes, int n_in,
                              void* d_out, int out_size)
{
    const float* x = (const float*)d_in[0];
    float* out = (float*)d_out;

    const int in_w = 8192;
    int batch = in_sizes[0] / in_w;
    int out_w = (batch > 0) ? out_size / batch : 0;

    bool fast = (batch > 0) &&
                (batch * in_w == in_sizes[0]) &&
                (out_w == in_w - 1) &&
                ((size_t)batch * (size_t)out_w == (size_t)out_size);

    if (fast) {
        binagg_row_kernel<<<batch, TPB>>>((const float4*)x, out);
    } else {
        int iw = in_sizes[0];
        int ow = out_size;
        for (int cand = 8192; cand >= 1; cand >>= 1) {
            if (in_sizes[0] % cand == 0) {
                int bb = in_sizes[0] / cand;
                if (bb > 0 && out_size % bb == 0) { iw = cand; ow = out_size / bb; break; }
            }
        }
        unsigned total = (unsigned)out_size;
        unsigned blocks = (total + 255) / 256;
        binagg_generic_kernel<<<blocks, 256>>>(x, out, iw, ow, total);
    }
}

// round 13
// speedup vs baseline: 1.0970x; 1.0394x over previous
#include <cuda_runtime.h>
#include <cuda_bf16.h>
#include <stdint.h>

#ifndef CLAMP_VAL
#define CLAMP_VAL 10000.0f
#endif

__device__ __forceinline__ float clampv(float v) {
    return fminf(fmaxf(v, -CLAMP_VAL), CLAMP_VAL);
}

// ---------------------------------------------------------------------------
// Fast path: in_w = 8192, out_w = 8191. One block per row, TPB=256.
// Aligned 128-bit on BOTH sides; per-row 4-byte phase (lead = row & 3).
// Overlap vector components come from lane t+1 via __shfl_down_sync instead
// of a second LDG.128. FIXED vs R12: uniform trip count (all lanes execute
// every iteration with the load index clamped in-row; stores predicated),
// so all shuffles run with a fully converged warp. The clamped inactive-lane
// load (xrow[min(v,2047)]) also supplies the correct overlap for the last
// active lane mid-warp. Lane 31's real overlap load is gated on 'active'.
// ---------------------------------------------------------------------------
constexpr int TPB = 256;

__global__ void __launch_bounds__(TPB)
binagg_row_kernel(const float4* __restrict__ x4, float* __restrict__ out)
{
    const unsigned r = blockIdx.x;
    const float4* xrow = x4 + (size_t)r * 2048u;           // 8192 floats / 4
    const float*  xs   = (const float*)xrow;
    const float2* xs2  = (const float2*)xrow;
    float*        orow = out + (size_t)r * 8191u;
    const int tid  = threadIdx.x;
    const int lane = tid & 31;
    const bool last_lane = (lane == 31);
    const int lead = (int)(r & 3u);                         // out-row phase

    // Head: cols 0..lead-1 (0..3 scalars)
    if (tid < lead) orow[tid] = clampv(__ldg(xs + tid));

    // Aligned out-vectors covering cols [lead, lead+4*count), max col <= 8189
    const int count = ((8186 - lead) >> 2) + 1;             // 2047 or 2046
    float4* ov = (float4*)(orow + lead);                    // 16B aligned
    const int n_iter = (count + TPB - 1) / TPB;             // uniform: 8

    if (lead == 0) {
        #pragma unroll 4
        for (int v = tid; v < count; v += TPB) {
            float4 a = __ldg(&xrow[v]);
            float4 s = { clampv(a.x), clampv(a.y), clampv(a.z), clampv(a.w) };
            __stcs(&ov[v], s);
        }
    } else if (lead == 1) {
        #pragma unroll 4
        for (int k = 0; k < n_iter; ++k) {
            int v = tid + k * TPB;
            bool active = (v < count);
            int vv = min(v, 2047);                          // in-row clamp
            float4 a  = __ldg(&xrow[vv]);
            float  bx = __shfl_down_sync(0xFFFFFFFFu, a.x, 1);
            if (last_lane && active) bx = __ldg(xs + 4 * v + 4);
            if (active) {
                float4 s = { clampv(a.y), clampv(a.z), clampv(a.w), clampv(bx) };
                __stcs(&ov[v], s);
            }
        }
    } else if (lead == 2) {
        #pragma unroll 4
        for (int k = 0; k < n_iter; ++k) {
            int v = tid + k * TPB;
            bool active = (v < count);
            int vv = min(v, 2047);
            float4 a  = __ldg(&xrow[vv]);
            float  bx = __shfl_down_sync(0xFFFFFFFFu, a.x, 1);
            float  by = __shfl_down_sync(0xFFFFFFFFu, a.y, 1);
            if (last_lane && active) {
                float2 b = __ldg(&xs2[2 * v + 2]);
                bx = b.x; by = b.y;
            }
            if (active) {
                float4 s = { clampv(a.z), clampv(a.w), clampv(bx), clampv(by) };
                __stcs(&ov[v], s);
            }
        }
    } else {
        #pragma unroll 4
        for (int k = 0; k < n_iter; ++k) {
            int v = tid + k * TPB;
            bool active = (v < count);
            int vv = min(v, 2047);
            float4 a  = __ldg(&xrow[vv]);
            float  bx = __shfl_down_sync(0xFFFFFFFFu, a.x, 1);
            float  by = __shfl_down_sync(0xFFFFFFFFu, a.y, 1);
            float  bz = __shfl_down_sync(0xFFFFFFFFu, a.z, 1);
            if (last_lane && active) {
                float2 b = __ldg(&xs2[2 * v + 2]);
                bx = b.x; by = b.y;
                bz = __ldg(xs + 4 * v + 6);
            }
            if (active) {
                float4 s = { clampv(a.w), clampv(bx), clampv(by), clampv(bz) };
                __stcs(&ov[v], s);
            }
        }
    }

    // Tail: cols [lead + 4*count, 8190]; col 8190 = mean of last two inputs
    const int tstart = lead + 4 * count;
    for (int c = tstart + tid; c <= 8190; c += TPB) {
        float val = (c == 8190)
                  ? 0.5f * (__ldg(xs + 8190) + __ldg(xs + 8191))
                  : __ldg(xs + c);
        orow[c] = clampv(val);
    }
}

// ---------------------------------------------------------------------------
// Generic fallback (any in_w/out_w): flat output indexing, scalar.
// ---------------------------------------------------------------------------
__global__ void __launch_bounds__(256)
binagg_generic_kernel(const float* __restrict__ x, float* __restrict__ out,
                      int in_w, int out_w, unsigned total)
{
    unsigned oo = blockIdx.x * blockDim.x + threadIdx.x;
    if (oo >= total) return;
    unsigned r = oo / (unsigned)out_w;
    unsigned c = oo - r * (unsigned)out_w;
    const float* xr = x + (size_t)r * (size_t)in_w;
    float val;
    if (c < (unsigned)(out_w - 1)) {
        val = __ldg(xr + c);
    } else {
        float s = 0.0f;
        for (int k = out_w - 1; k < in_w; ++k) s += __ldg(xr + k);
        val = s / (float)(in_w - out_w + 1);
    }
    out[oo] = clampv(val);
}

extern "C" void kernel_launch(void* const* d_in, const int* in_sizes, int n_in,
                              void* d_out, int out_size)
{
    const float* x = (const float*)d_in[0];
    float* out = (float*)d_out;

    const int in_w = 8192;
    int batch = in_sizes[0] / in_w;
    int out_w = (batch > 0) ? out_size / batch : 0;

    bool fast = (batch > 0) &&
                (batch * in_w == in_sizes[0]) &&
                (out_w == in_w - 1) &&
                ((size_t)batch * (size_t)out_w == (size_t)out_size);

    if (fast) {
        binagg_row_kernel<<<batch, TPB>>>((const float4*)x, out);
    } else {
        int iw = in_sizes[0];
        int ow = out_size;
        for (int cand = 8192; cand >= 1; cand >>= 1) {
            if (in_sizes[0] % cand == 0) {
                int bb = in_sizes[0] / cand;
                if (bb > 0 && out_size % bb == 0) { iw = cand; ow = out_size / bb; break; }
            }
        }
        unsigned total = (unsigned)out_size;
        unsigned blocks = (total + 255) / 256;
        binagg_generic_kernel<<<blocks, 256>>>(x, out, iw, ow, total);
    }
}